// round 1
// baseline (speedup 1.0000x reference)
#include <cuda_runtime.h>
#include <math.h>

// Fully-fused NeRF forward, fp32 baseline.
// One CTA of 256 threads processes TILE=64 points through all layers.
// Activations live in SMEM; weights are staged per-K-chunk into SMEM.
// Micro-tile: each thread accumulates 8 points x 8 output columns in registers.

#define THREADS 256
#define TILE    64
#define HS      257   // h_s row stride (pad to kill 32-way LDS conflicts)
#define KC      32    // K-chunk rows staged into SMEM per step

// -------------------------------------------------------------------------
// Accumulate a K-segment into acc[8][8] for a 256-output-column layer.
// Wg row-major with row stride ldw, column offset co. Rows kbase..kbase+Kseg.
// src: SMEM activation segment with row stride st (per point).
// -------------------------------------------------------------------------
__device__ __forceinline__ void accum_seg256(
    float (&acc)[8][8],
    const float* __restrict__ Wg, int ldw, int co, int kbase,
    const float* __restrict__ src, int st, int Kseg,
    float* __restrict__ w_s, int p0, int c0, int tid)
{
    for (int k0 = 0; k0 < Kseg; k0 += KC) {
        const int kc = min(KC, Kseg - k0);
        __syncthreads();  // protect w_s from previous use
        for (int idx = tid; idx < kc * 256; idx += THREADS) {
            const int r = idx >> 8;
            const int c = idx & 255;
            w_s[idx] = Wg[(kbase + k0 + r) * ldw + co + c];
        }
        __syncthreads();
        const float* srcp = src + k0;
        if (kc == KC) {
            #pragma unroll 8
            for (int kk = 0; kk < KC; kk++) {
                float a[8];
                #pragma unroll
                for (int i = 0; i < 8; i++) a[i] = srcp[(p0 + i) * st + kk];
                const float4 bv0 = *reinterpret_cast<const float4*>(w_s + kk * 256 + c0);
                const float4 bv1 = *reinterpret_cast<const float4*>(w_s + kk * 256 + c0 + 4);
                const float b[8] = {bv0.x, bv0.y, bv0.z, bv0.w, bv1.x, bv1.y, bv1.z, bv1.w};
                #pragma unroll
                for (int i = 0; i < 8; i++)
                    #pragma unroll
                    for (int j = 0; j < 8; j++)
                        acc[i][j] = fmaf(a[i], b[j], acc[i][j]);
            }
        } else {
            for (int kk = 0; kk < kc; kk++) {
                float a[8];
                #pragma unroll
                for (int i = 0; i < 8; i++) a[i] = srcp[(p0 + i) * st + kk];
                const float4 bv0 = *reinterpret_cast<const float4*>(w_s + kk * 256 + c0);
                const float4 bv1 = *reinterpret_cast<const float4*>(w_s + kk * 256 + c0 + 4);
                const float b[8] = {bv0.x, bv0.y, bv0.z, bv0.w, bv1.x, bv1.y, bv1.z, bv1.w};
                #pragma unroll
                for (int i = 0; i < 8; i++)
                    #pragma unroll
                    for (int j = 0; j < 8; j++)
                        acc[i][j] = fmaf(a[i], b[j], acc[i][j]);
            }
        }
    }
}

// Dense layer with 256 output columns: out = act(concat(segA, segB) @ W + b)
// Writes result to h_s[p*HS + c].
__device__ __forceinline__ void layer256(
    const float* __restrict__ Wg, const float* __restrict__ bg, int ldw, int co,
    const float* __restrict__ segA, int sA, int KA,
    const float* __restrict__ segB, int sB, int KB,
    float* __restrict__ w_s, float* __restrict__ h_s, bool do_relu, int tid)
{
    float acc[8][8];
    #pragma unroll
    for (int i = 0; i < 8; i++)
        #pragma unroll
        for (int j = 0; j < 8; j++) acc[i][j] = 0.f;

    const int p0 = (tid & 7) * 8;
    const int c0 = (tid >> 3) * 8;

    accum_seg256(acc, Wg, ldw, co, 0, segA, sA, KA, w_s, p0, c0, tid);
    if (KB > 0)
        accum_seg256(acc, Wg, ldw, co, KA, segB, sB, KB, w_s, p0, c0, tid);

    __syncthreads();  // all reads of h_s done before overwrite
    #pragma unroll
    for (int j = 0; j < 8; j++) {
        const float bb = bg[co + c0 + j];
        #pragma unroll
        for (int i = 0; i < 8; i++) {
            float v = acc[i][j] + bb;
            if (do_relu) v = fmaxf(v, 0.f);
            h_s[(p0 + i) * HS + c0 + j] = v;
        }
    }
    __syncthreads();
}

// Color-head layer: 128 output columns. Micro-tile 4 pts x 8 cols.
__device__ __forceinline__ void accum_seg128(
    float (&acc)[4][8],
    const float* __restrict__ Wg, int kbase,
    const float* __restrict__ src, int st, int Kseg,
    float* __restrict__ w_s, int p0, int c0, int tid)
{
    for (int k0 = 0; k0 < Kseg; k0 += KC) {
        const int kc = min(KC, Kseg - k0);
        __syncthreads();
        for (int idx = tid; idx < kc * 128; idx += THREADS) {
            const int r = idx >> 7;
            const int c = idx & 127;
            w_s[idx] = Wg[(kbase + k0 + r) * 128 + c];
        }
        __syncthreads();
        const float* srcp = src + k0;
        for (int kk = 0; kk < kc; kk++) {
            float a[4];
            #pragma unroll
            for (int i = 0; i < 4; i++) a[i] = srcp[(p0 + i) * st + kk];
            const float4 bv0 = *reinterpret_cast<const float4*>(w_s + kk * 128 + c0);
            const float4 bv1 = *reinterpret_cast<const float4*>(w_s + kk * 128 + c0 + 4);
            const float b[8] = {bv0.x, bv0.y, bv0.z, bv0.w, bv1.x, bv1.y, bv1.z, bv1.w};
            #pragma unroll
            for (int i = 0; i < 4; i++)
                #pragma unroll
                for (int j = 0; j < 8; j++)
                    acc[i][j] = fmaf(a[i], b[j], acc[i][j]);
        }
    }
}

__device__ __forceinline__ void layer128(
    const float* __restrict__ Wg, const float* __restrict__ bg,
    const float* __restrict__ segA, int sA, int KA,
    const float* __restrict__ segB, int sB, int KB,
    float* __restrict__ w_s, float* __restrict__ h_s, int tid)
{
    float acc[4][8];
    #pragma unroll
    for (int i = 0; i < 4; i++)
        #pragma unroll
        for (int j = 0; j < 8; j++) acc[i][j] = 0.f;

    const int p0 = (tid & 15) * 4;
    const int c0 = (tid >> 4) * 8;

    accum_seg128(acc, Wg, 0, segA, sA, KA, w_s, p0, c0, tid);
    accum_seg128(acc, Wg, KA, segB, sB, KB, w_s, p0, c0, tid);

    __syncthreads();
    #pragma unroll
    for (int j = 0; j < 8; j++) {
        const float bb = bg[c0 + j];
        #pragma unroll
        for (int i = 0; i < 4; i++) {
            float v = fmaxf(acc[i][j] + bb, 0.f);  // ReLU
            h_s[(p0 + i) * HS + c0 + j] = v;
        }
    }
    __syncthreads();
}

__global__ void __launch_bounds__(THREADS, 1) nerf_fused_kernel(
    const float* __restrict__ pts, const float* __restrict__ dirs,
    const float* __restrict__ W0, const float* __restrict__ b0,
    const float* __restrict__ W1, const float* __restrict__ b1,
    const float* __restrict__ W2, const float* __restrict__ b2,
    const float* __restrict__ W3, const float* __restrict__ b3,
    const float* __restrict__ W4, const float* __restrict__ b4,
    const float* __restrict__ W5, const float* __restrict__ b5,
    const float* __restrict__ W6, const float* __restrict__ b6,
    const float* __restrict__ W7, const float* __restrict__ b7,
    const float* __restrict__ Wc, const float* __restrict__ bc,
    const float* __restrict__ Wo, const float* __restrict__ bo,
    float* __restrict__ out_color, float* __restrict__ out_sigma, int P)
{
    extern __shared__ float sm[];
    float* e_s = sm;                    // [64][39]  xyz harmonic embedding
    float* d_s = e_s + TILE * 39;       // [64][27]  dir harmonic embedding
    float* h_s = d_s + TILE * 27;       // [64][HS]  activations
    float* w_s = h_s + TILE * HS;       // [KC][256] staged weights

    const int tid  = threadIdx.x;
    const int base = blockIdx.x * TILE;

    // ---- Harmonic embeddings (one thread per point) ----
    if (tid < TILE) {
        const int n = base + tid;
        const float x = pts[n * 3 + 0];
        const float y = pts[n * 3 + 1];
        const float z = pts[n * 3 + 2];
        float* ep = e_s + tid * 39;
        #pragma unroll
        for (int h = 0; h < 6; h++) {
            const float f = (float)(1 << h);
            float sx, cx, sy, cy, sz, cz;
            sincosf(x * f, &sx, &cx);
            sincosf(y * f, &sy, &cy);
            sincosf(z * f, &sz, &cz);
            ep[0  + h] = sx; ep[6  + h] = sy; ep[12 + h] = sz;
            ep[18 + h] = cx; ep[24 + h] = cy; ep[30 + h] = cz;
        }
        ep[36] = x; ep[37] = y; ep[38] = z;

        const int r = n / P;
        const float dx = dirs[r * 3 + 0];
        const float dy = dirs[r * 3 + 1];
        const float dz = dirs[r * 3 + 2];
        float* dp = d_s + tid * 27;
        #pragma unroll
        for (int h = 0; h < 4; h++) {
            const float f = (float)(1 << h);
            float sx, cx, sy, cy, sz, cz;
            sincosf(dx * f, &sx, &cx);
            sincosf(dy * f, &sy, &cy);
            sincosf(dz * f, &sz, &cz);
            dp[0  + h] = sx; dp[4  + h] = sy; dp[8  + h] = sz;
            dp[12 + h] = cx; dp[16 + h] = cy; dp[20 + h] = cz;
        }
        dp[24] = dx; dp[25] = dy; dp[26] = dz;
    }
    __syncthreads();

    // ---- Trunk ----
    layer256(W0, b0, 256, 0, e_s, 39, 39,  nullptr, 0, 0,  w_s, h_s, true, tid);
    layer256(W1, b1, 256, 0, h_s, HS, 256, nullptr, 0, 0,  w_s, h_s, true, tid);
    layer256(W2, b2, 256, 0, h_s, HS, 256, nullptr, 0, 0,  w_s, h_s, true, tid);
    layer256(W3, b3, 256, 0, h_s, HS, 256, nullptr, 0, 0,  w_s, h_s, true, tid);
    layer256(W4, b4, 256, 0, h_s, HS, 256, nullptr, 0, 0,  w_s, h_s, true, tid);
    // skip-concat layer: [h, e] @ W5
    layer256(W5, b5, 256, 0, h_s, HS, 256, e_s, 39, 39,    w_s, h_s, true, tid);
    layer256(W6, b6, 256, 0, h_s, HS, 256, nullptr, 0, 0,  w_s, h_s, true, tid);

    // ---- Sigma: column 0 of layer 7, from h6 (still in h_s) ----
    if (tid < TILE) {
        const int n = base + tid;
        float s = b7[0];
        const float* hp = h_s + tid * HS;
        #pragma unroll 4
        for (int k = 0; k < 256; k++) s = fmaf(hp[k], W7[k * 257], s);
        out_sigma[n] = fmaxf(s, 0.f);
    }
    // (no sync needed: both sigma and layer7 k-loop only READ h_s; layer7's
    //  writeback is gated by its own __syncthreads)

    // ---- Layer 7 columns 1..256 (no ReLU): h7[1:257] -> h_s ----
    layer256(W7, b7, 257, 1, h_s, HS, 256, nullptr, 0, 0,  w_s, h_s, false, tid);

    // ---- Color head: [h7[1:257], d] @ Wc, ReLU -> h_s cols 0..127 ----
    layer128(Wc, bc, h_s, HS, 256, d_s, 27, 27, w_s, h_s, tid);

    // ---- Output: sigmoid(h @ Wo + bo), 3 cols ----
    if (tid < TILE * 3) {
        const int p = tid / 3;
        const int c = tid % 3;
        float s = bo[c];
        const float* hp = h_s + p * HS;
        #pragma unroll 4
        for (int k = 0; k < 128; k++) s = fmaf(hp[k], Wo[k * 3 + c], s);
        out_color[(base + p) * 3 + c] = 1.f / (1.f + expf(-s));
    }
}

extern "C" void kernel_launch(void* const* d_in, const int* in_sizes, int n_in,
                              void* d_out, int out_size)
{
    const float* pts  = (const float*)d_in[0];
    const float* dirs = (const float*)d_in[1];
    const float* W0 = (const float*)d_in[2];   const float* b0 = (const float*)d_in[3];
    const float* W1 = (const float*)d_in[4];   const float* b1 = (const float*)d_in[5];
    const float* W2 = (const float*)d_in[6];   const float* b2 = (const float*)d_in[7];
    const float* W3 = (const float*)d_in[8];   const float* b3 = (const float*)d_in[9];
    const float* W4 = (const float*)d_in[10];  const float* b4 = (const float*)d_in[11];
    const float* W5 = (const float*)d_in[12];  const float* b5 = (const float*)d_in[13];
    const float* W6 = (const float*)d_in[14];  const float* b6 = (const float*)d_in[15];
    const float* W7 = (const float*)d_in[16];  const float* b7 = (const float*)d_in[17];
    const float* Wc = (const float*)d_in[18];  const float* bc = (const float*)d_in[19];
    const float* Wo = (const float*)d_in[20];  const float* bo = (const float*)d_in[21];

    const int N = in_sizes[0] / 3;        // 131072 points
    const int R = in_sizes[1] / 3;        // 2048 rays
    const int P = N / R;                  // 64 samples per ray

    float* out_color = (float*)d_out;               // [N,3] first (tuple order)
    float* out_sigma = out_color + (size_t)N * 3;   // [N,1] after

    const int smem_bytes = (TILE * 39 + TILE * 27 + TILE * HS + KC * 256) * sizeof(float);
    cudaFuncSetAttribute(nerf_fused_kernel,
                         cudaFuncAttributeMaxDynamicSharedMemorySize, smem_bytes);

    nerf_fused_kernel<<<N / TILE, THREADS, smem_bytes>>>(
        pts, dirs,
        W0, b0, W1, b1, W2, b2, W3, b3, W4, b4, W5, b5, W6, b6, W7, b7,
        Wc, bc, Wo, bo,
        out_color, out_sigma, P);
}